// round 3
// baseline (speedup 1.0000x reference)
#include <cuda_runtime.h>
#include <cuda_fp16.h>
#include <stdint.h>

// ---------------------------------------------------------------------------
// Problem constants
// ---------------------------------------------------------------------------
#define N_TOK 65536
#define DIM   1024
#define S_SEM 200
#define NPACK 352      // 1 cls + 12 fused-sem + 324 bbox + 15 zero pad
#define NSC   81
#define NBB   324
#define BM    128
#define BK    64
#define NKCH  (DIM / BK)     // 16
#define THREADS 512
#define AROWF 68             // A smem row: 64 floats + 4 pad

// Packed fp16 weights + fp32 bias (built by prep kernel every launch)
__device__ __half g_Wp[NPACK * DIM];
__device__ float  g_bp[NPACK];

// Selected class indices (0-based into the 80 class cols): {i-1 : i in IGNORE2} U {79}
__constant__ int c_sel[12] = {1, 2, 16, 18, 29, 37, 47, 53, 63, 68, 72, 79};

__device__ __forceinline__ constexpr bool cls_keep(int j) {
    return j == 1 || j == 2 || j == 16 || j == 18 || j == 29 || j == 37 ||
           j == 47 || j == 53 || j == 63 || j == 68 || j == 72 || j == 79;
}

__device__ __forceinline__ uint32_t smem_u32(const void* p) {
    uint32_t a;
    asm("{ .reg .u64 t; cvta.to.shared.u64 t, %1; cvt.u32.u64 %0, t; }"
        : "=r"(a) : "l"(p));
    return a;
}

// ---------------------------------------------------------------------------
// SMEM layout (bytes):
//   [0, 1536)            bias (352 f32, padded)
//   [1536, 71168)        A32[2][128][68] f32
//   [71168, 161280)      B16[2][352*128B] fp16, SW128-swizzled rows
// ---------------------------------------------------------------------------
#define SMO_BIAS 0
#define SMO_A    1536
#define SMO_B    71168
#define SM_TOTAL 161280

// ---------------------------------------------------------------------------
// Prep: pack [W_cls ; sem_matrix[sel] @ W_sem / S ; W_bbox ; 0-pad] -> fp16
// ---------------------------------------------------------------------------
__global__ void prep_kernel(const float* __restrict__ W_cls,
                            const float* __restrict__ b_cls,
                            const float* __restrict__ W_sem,
                            const float* __restrict__ b_sem,
                            const float* __restrict__ W_bbox,
                            const float* __restrict__ b_bbox,
                            const float* __restrict__ sem_m) {
    const int r = blockIdx.x;
    const int tid = threadIdx.x;
    if (r == 0) {
        for (int d = tid; d < DIM; d += blockDim.x)
            g_Wp[d] = __float2half(W_cls[d]);
        if (tid == 0) g_bp[0] = b_cls[0];
    } else if (r <= 12) {
        const int sj = c_sel[r - 1];
        const float* M = sem_m + (size_t)sj * S_SEM;
        for (int d = tid; d < DIM; d += blockDim.x) {
            float acc = 0.0f;
            for (int s = 0; s < S_SEM; s++)
                acc += M[s] * W_sem[(size_t)s * DIM + d];
            g_Wp[(size_t)r * DIM + d] = __float2half(acc * (1.0f / S_SEM));
        }
        if (tid == 0) {
            float a = 0.0f;
            for (int s = 0; s < S_SEM; s++) a += M[s] * b_sem[s];
            g_bp[r] = a * (1.0f / S_SEM);
        }
    } else if (r < 13 + NBB) {
        const int c = r - 13;
        for (int d = tid; d < DIM; d += blockDim.x)
            g_Wp[(size_t)r * DIM + d] = __float2half(W_bbox[(size_t)c * DIM + d]);
        if (tid == 0) g_bp[r] = b_bbox[c];
    } else {
        for (int d = tid; d < DIM; d += blockDim.x)
            g_Wp[(size_t)r * DIM + d] = __float2half(0.0f);
        if (tid == 0) g_bp[r] = 0.0f;
    }
}

// ---------------------------------------------------------------------------
// Main GEMM: [128, 1024] x [1024, 352] per CTA via mma.sync m16n8k16 fp16
// ---------------------------------------------------------------------------
__global__ void __launch_bounds__(THREADS, 1)
fpn_gemm(const float* __restrict__ x, float* __restrict__ out) {
    extern __shared__ char smem[];
    float* s_bias = (float*)(smem + SMO_BIAS);
    float* sA = (float*)(smem + SMO_A);
    const uint32_t sbB = smem_u32(smem + SMO_B);

    const int tid = threadIdx.x;
    const int wid = tid >> 5, lid = tid & 31;
    const int wm = wid >> 2, wn = wid & 3;        // 4 warps M x 4 warps N
    const int mbase = blockIdx.x * BM;
    const int q = lid >> 2, t = lid & 3;

    for (int i = tid; i < NPACK; i += THREADS) s_bias[i] = g_bp[i];

    float acc[2][11][4];
#pragma unroll
    for (int a = 0; a < 2; a++)
#pragma unroll
        for (int b = 0; b < 11; b++)
#pragma unroll
            for (int e = 0; e < 4; e++) acc[a][b][e] = 0.0f;

    const uint32_t sbA = smem_u32(sA);

    // --- stage chunk kc into buffer kc&1 via cp.async ---
    auto stage = [&](int kc) {
        const int buf = kc & 1;
        // A: 128 rows x 64 f32 (16 x 16B per row), padded smem rows
        const char* xs = (const char*)(x + (size_t)mbase * DIM + kc * BK);
        const uint32_t adst = sbA + buf * (BM * AROWF * 4);
#pragma unroll
        for (int it = 0; it < 4; it++) {
            int i = it * THREADS + tid;
            int r = i >> 4, j = i & 15;
            uint32_t d = adst + r * (AROWF * 4) + j * 16;
            const char* s = xs + (size_t)r * (DIM * 4) + j * 16;
            asm volatile("cp.async.cg.shared.global [%0], [%1], 16;" :: "r"(d), "l"(s));
        }
        // B: 352 rows x 64 fp16 (8 x 16B per row), SW128 swizzle
        const char* ws = (const char*)g_Wp + (size_t)kc * (BK * 2);
        const uint32_t bdst = sbB + buf * (NPACK * 128);
        for (int i = tid; i < NPACK * 8; i += THREADS) {
            int r = i >> 3, j = i & 7;
            uint32_t off = (uint32_t)(r * 128 + j * 16);
            uint32_t d = bdst + (off ^ ((off >> 3) & 0x70));
            const char* s = ws + (size_t)r * (DIM * 2) + j * 16;
            asm volatile("cp.async.cg.shared.global [%0], [%1], 16;" :: "r"(d), "l"(s));
        }
        asm volatile("cp.async.commit_group;" ::: "memory");
    };

    stage(0);

    for (int kc = 0; kc < NKCH; kc++) {
        if (kc + 1 < NKCH) {
            stage(kc + 1);
            asm volatile("cp.async.wait_group 1;" ::: "memory");
        } else {
            asm volatile("cp.async.wait_group 0;" ::: "memory");
        }
        __syncthreads();

        const int buf = kc & 1;
        const float* Abuf = sA + buf * (BM * AROWF);
        const uint32_t Bbuf = sbB + buf * (NPACK * 128);

#pragma unroll
        for (int ks = 0; ks < 4; ks++) {
            // ---- A fragments: LDS fp32 pairs, cvt+pack to fp16x2 ----
            uint32_t af[2][4];
#pragma unroll
            for (int mf = 0; mf < 2; mf++) {
                const float* base = Abuf + (wm * 32 + mf * 16 + q) * AROWF + ks * 16 + t * 2;
                float2 v0 = *(const float2*)(base);                  // A[q][2t..]
                float2 v1 = *(const float2*)(base + 8 * AROWF);      // A[q+8][2t..]
                float2 v2 = *(const float2*)(base + 8);              // A[q][2t+8..]
                float2 v3 = *(const float2*)(base + 8 * AROWF + 8);  // A[q+8][2t+8..]
                union { __half2 h; uint32_t u; } p0, p1, p2, p3;
                p0.h = __floats2half2_rn(v0.x, v0.y);
                p1.h = __floats2half2_rn(v1.x, v1.y);
                p2.h = __floats2half2_rn(v2.x, v2.y);
                p3.h = __floats2half2_rn(v3.x, v3.y);
                af[mf][0] = p0.u; af[mf][1] = p1.u; af[mf][2] = p2.u; af[mf][3] = p3.u;
            }
            // ---- B fragments + MMA ----
            // B smem is N-major (K contiguous): non-trans ldmatrix gives thread t
            // M[row=n=t/4][col=k=2(t%4)+j] == required b-fragment. Lanes 0-7 ->
            // matrix0 (k 0..7), lanes 8-15 -> matrix1 (k 8..15).
#pragma unroll
            for (int nf = 0; nf < 11; nf++) {
                int row = wn * 88 + nf * 8 + (lid & 7);
                uint32_t off = (uint32_t)(row * 128 + ks * 32 + ((lid >> 3) & 1) * 16);
                uint32_t addr = Bbuf + (off ^ ((off >> 3) & 0x70));
                uint32_t b0, b1;
                asm volatile("ldmatrix.sync.aligned.m8n8.x2.shared.b16 {%0,%1}, [%2];"
                             : "=r"(b0), "=r"(b1) : "r"(addr));
#pragma unroll
                for (int mf = 0; mf < 2; mf++) {
                    asm volatile(
                        "mma.sync.aligned.m16n8k16.row.col.f32.f16.f16.f32 "
                        "{%0,%1,%2,%3},{%4,%5,%6,%7},{%8,%9},{%0,%1,%2,%3};"
                        : "+f"(acc[mf][nf][0]), "+f"(acc[mf][nf][1]),
                          "+f"(acc[mf][nf][2]), "+f"(acc[mf][nf][3])
                        : "r"(af[mf][0]), "r"(af[mf][1]), "r"(af[mf][2]), "r"(af[mf][3]),
                          "r"(b0), "r"(b1));
                }
            }
        }
        __syncthreads();
    }

    // ---- zero the 68 masked class-score columns ----
    {
        int r = tid >> 2, sub = tid & 3;
        float* srow = out + (size_t)(mbase + r) * NSC;
#pragma unroll
        for (int j = sub; j < 80; j += 4)
            if (!cls_keep(j)) srow[1 + j] = 0.0f;
    }

    // ---- scatter accumulators (+bias) ----
#pragma unroll
    for (int mf = 0; mf < 2; mf++) {
#pragma unroll
        for (int half = 0; half < 2; half++) {
            const int m = mbase + wm * 32 + mf * 16 + q + half * 8;
            float* srow = out + (size_t)m * NSC;
            float* brow = out + (size_t)N_TOK * NSC + (size_t)m * NBB;
#pragma unroll
            for (int nf = 0; nf < 11; nf++) {
#pragma unroll
                for (int e = 0; e < 2; e++) {
                    const int c = wn * 88 + nf * 8 + t * 2 + e;
                    float v = acc[mf][nf][half * 2 + e] + s_bias[c];
                    if (c == 0)        srow[0] = v;
                    else if (c <= 12)  srow[1 + c_sel[c - 1]] = v;
                    else if (c <= 336) brow[c - 13] = v;
                }
            }
        }
    }
}

// ---------------------------------------------------------------------------
// Launch
// ---------------------------------------------------------------------------
extern "C" void kernel_launch(void* const* d_in, const int* in_sizes, int n_in,
                              void* d_out, int out_size) {
    const float* x      = (const float*)d_in[0];
    const float* W_cls  = (const float*)d_in[1];
    const float* b_cls  = (const float*)d_in[2];
    const float* W_sem  = (const float*)d_in[3];
    const float* b_sem  = (const float*)d_in[4];
    const float* W_bbox = (const float*)d_in[5];
    const float* b_bbox = (const float*)d_in[6];
    const float* sem_m  = (const float*)d_in[7];
    float* out = (float*)d_out;

    cudaFuncSetAttribute(fpn_gemm, cudaFuncAttributeMaxDynamicSharedMemorySize, SM_TOTAL);

    prep_kernel<<<NPACK, 256>>>(W_cls, b_cls, W_sem, b_sem, W_bbox, b_bbox, sem_m);
    fpn_gemm<<<N_TOK / BM, THREADS, SM_TOTAL>>>(x, out);
}

// round 4
// speedup vs baseline: 1.6870x; 1.6870x over previous
#include <cuda_runtime.h>
#include <cuda_fp16.h>
#include <stdint.h>

// ---------------------------------------------------------------------------
// Problem constants
// ---------------------------------------------------------------------------
#define N_TOK 65536
#define DIM   1024
#define S_SEM 200
#define NPACK 352      // 1 cls + 12 fused-sem + 324 bbox + 15 zero pad
#define NSC   81
#define NBB   324
#define BM    128
#define BK    64
#define NKCH  (DIM / BK)     // 16
#define THREADS 512
#define AROWF 68             // A32 smem row: 64 floats + 4 pad

// Packed fp16 weights + fp32 bias (built by prep kernel every launch)
__device__ __half g_Wp[NPACK * DIM];
__device__ float  g_bp[NPACK];

// Selected class indices (0-based into the 80 class cols): {i-1 : i in IGNORE2} U {79}
__constant__ int c_sel[12] = {1, 2, 16, 18, 29, 37, 47, 53, 63, 68, 72, 79};

__device__ __forceinline__ constexpr bool cls_keep(int j) {
    return j == 1 || j == 2 || j == 16 || j == 18 || j == 29 || j == 37 ||
           j == 47 || j == 53 || j == 63 || j == 68 || j == 72 || j == 79;
}

__device__ __forceinline__ uint32_t smem_u32(const void* p) {
    uint32_t a;
    asm("{ .reg .u64 t; cvta.to.shared.u64 t, %1; cvt.u32.u64 %0, t; }"
        : "=r"(a) : "l"(p));
    return a;
}

// ---------------------------------------------------------------------------
// SMEM layout (bytes)
// ---------------------------------------------------------------------------
#define SMO_BIAS 0                                   // 352 f32 (+pad) = 1536
#define SMO_A32  1536                                // 2 x 128 x 68 f32 = 69632
#define SMO_A16  (SMO_A32 + 2 * BM * AROWF * 4)      // 71168; 128 x 128B = 16384
#define SMO_B    (SMO_A16 + BM * 128)                // 87552; 2 x 352 x 128B = 90112
#define SM_TOTAL (SMO_B + 2 * NPACK * 128)           // 177664

// ---------------------------------------------------------------------------
// Prep: pack [W_cls ; sem_matrix[sel] @ W_sem / S ; W_bbox ; 0-pad] -> fp16
// Blocks 0..47: sem fusion (12 rows x 4 d-chunks of 256). Blocks 48..399: copies.
// ---------------------------------------------------------------------------
#define SEM_BLKS 48
__global__ void prep_kernel(const float* __restrict__ W_cls,
                            const float* __restrict__ b_cls,
                            const float* __restrict__ W_sem,
                            const float* __restrict__ b_sem,
                            const float* __restrict__ W_bbox,
                            const float* __restrict__ b_bbox,
                            const float* __restrict__ sem_m) {
    const int tid = threadIdx.x;
    const int bid = blockIdx.x;
    if (bid < SEM_BLKS) {
        __shared__ float sM[S_SEM];
        const int r = (bid >> 2) + 1;            // packed row 1..12
        const int chunk = bid & 3;
        const int sj = c_sel[r - 1];
        const float* M = sem_m + (size_t)sj * S_SEM;
        if (tid < S_SEM) sM[tid] = M[tid];
        __syncthreads();
        const int d = chunk * 256 + tid;
        const float* Wcol = W_sem + d;
        float a0 = 0.f, a1 = 0.f, a2 = 0.f, a3 = 0.f;
#pragma unroll 4
        for (int s = 0; s < S_SEM; s += 4) {
            a0 += sM[s + 0] * Wcol[(size_t)(s + 0) * DIM];
            a1 += sM[s + 1] * Wcol[(size_t)(s + 1) * DIM];
            a2 += sM[s + 2] * Wcol[(size_t)(s + 2) * DIM];
            a3 += sM[s + 3] * Wcol[(size_t)(s + 3) * DIM];
        }
        g_Wp[(size_t)r * DIM + d] = __float2half(((a0 + a1) + (a2 + a3)) * (1.0f / S_SEM));
        if (chunk == 0 && tid < 32) {
            float p = 0.f;
            for (int s = tid; s < S_SEM; s += 32) p += sM[s] * b_sem[s];
#pragma unroll
            for (int o = 16; o > 0; o >>= 1) p += __shfl_xor_sync(0xffffffffu, p, o);
            if (tid == 0) g_bp[r] = p * (1.0f / S_SEM);
        }
    } else {
        const int r = bid - SEM_BLKS;            // 0..351
        if (r >= 1 && r <= 12) return;           // sem blocks own these
        __half* dst = g_Wp + (size_t)r * DIM;
        if (r == 0) {
            const float4* s = (const float4*)W_cls;
#pragma unroll
            for (int i = 0; i < 1; i++) {
                float4 v = s[tid];
                ((__half2*)dst)[tid * 2 + 0] = __floats2half2_rn(v.x, v.y);
                ((__half2*)dst)[tid * 2 + 1] = __floats2half2_rn(v.z, v.w);
            }
            if (tid == 0) g_bp[0] = b_cls[0];
        } else if (r < 13 + NBB) {
            const int c = r - 13;
            const float4* s = (const float4*)(W_bbox + (size_t)c * DIM);
            float4 v = s[tid];
            ((__half2*)dst)[tid * 2 + 0] = __floats2half2_rn(v.x, v.y);
            ((__half2*)dst)[tid * 2 + 1] = __floats2half2_rn(v.z, v.w);
            if (tid == 0) g_bp[r] = b_bbox[c];
        } else {
            ((__half2*)dst)[tid * 2 + 0] = __floats2half2_rn(0.f, 0.f);
            ((__half2*)dst)[tid * 2 + 1] = __floats2half2_rn(0.f, 0.f);
            if (tid == 0) g_bp[r] = 0.0f;
        }
    }
}

// ---------------------------------------------------------------------------
// Main GEMM: [128, 1024] x [1024, 352] per CTA via mma.sync m16n8k16 fp16
// ---------------------------------------------------------------------------
__global__ void __launch_bounds__(THREADS, 1)
fpn_gemm(const float* __restrict__ x, float* __restrict__ out) {
    extern __shared__ char smem[];
    float* s_bias = (float*)(smem + SMO_BIAS);
    float* sA32 = (float*)(smem + SMO_A32);
    const uint32_t sbA32 = smem_u32(smem + SMO_A32);
    const uint32_t sbA16 = smem_u32(smem + SMO_A16);
    const uint32_t sbB   = smem_u32(smem + SMO_B);

    const int tid = threadIdx.x;
    const int wid = tid >> 5, lid = tid & 31;
    const int wm = wid >> 2, wn = wid & 3;        // 4 warps M x 4 warps N
    const int mbase = blockIdx.x * BM;
    const int q = lid >> 2, t = lid & 3;

    for (int i = tid; i < NPACK; i += THREADS) s_bias[i] = g_bp[i];

    float acc[2][11][4];
#pragma unroll
    for (int a = 0; a < 2; a++)
#pragma unroll
        for (int b = 0; b < 11; b++)
#pragma unroll
            for (int e = 0; e < 4; e++) acc[a][b][e] = 0.0f;

    // --- stage chunk kc into buffer kc&1 via cp.async ---
    auto stage = [&](int kc) {
        const int buf = kc & 1;
        const char* xs = (const char*)(x + (size_t)mbase * DIM + kc * BK);
        const uint32_t adst = sbA32 + buf * (BM * AROWF * 4);
#pragma unroll
        for (int it = 0; it < 4; it++) {
            int i = it * THREADS + tid;
            int r = i >> 4, j = i & 15;
            uint32_t d = adst + r * (AROWF * 4) + j * 16;
            const char* s = xs + (size_t)r * (DIM * 4) + j * 16;
            asm volatile("cp.async.cg.shared.global [%0], [%1], 16;" :: "r"(d), "l"(s));
        }
        const char* ws = (const char*)g_Wp + (size_t)kc * (BK * 2);
        const uint32_t bdst = sbB + buf * (NPACK * 128);
        for (int i = tid; i < NPACK * 8; i += THREADS) {
            int r = i >> 3, j = i & 7;
            uint32_t off = (uint32_t)(r * 128 + j * 16);
            uint32_t d = bdst + (off ^ ((off >> 3) & 0x70));
            const char* s = ws + (size_t)r * (DIM * 2) + j * 16;
            asm volatile("cp.async.cg.shared.global [%0], [%1], 16;" :: "r"(d), "l"(s));
        }
        asm volatile("cp.async.commit_group;" ::: "memory");
    };

    stage(0);

    for (int kc = 0; kc < NKCH; kc++) {
        if (kc + 1 < NKCH) {
            stage(kc + 1);
            asm volatile("cp.async.wait_group 1;" ::: "memory");
        } else {
            asm volatile("cp.async.wait_group 0;" ::: "memory");
        }
        __syncthreads();

        const int buf = kc & 1;

        // ---- convert A32[buf] -> A16 (SW128 swizzled, 128B rows) ----
        {
            const int r = tid >> 2, j = tid & 3;          // 128 rows x 4 threads
            const float* src = sA32 + buf * (BM * AROWF) + r * AROWF + j * 16;
            float4 v0 = *(const float4*)(src + 0);
            float4 v1 = *(const float4*)(src + 4);
            float4 v2 = *(const float4*)(src + 8);
            float4 v3 = *(const float4*)(src + 12);
            union { __half2 h[2]; uint2 u; } s0, s1;
            union { uint4 q; } w0, w1;
            s0.h[0] = __floats2half2_rn(v0.x, v0.y);
            s0.h[1] = __floats2half2_rn(v0.z, v0.w);
            w0.q.x = s0.u.x; w0.q.y = s0.u.y;
            s1.h[0] = __floats2half2_rn(v1.x, v1.y);
            s1.h[1] = __floats2half2_rn(v1.z, v1.w);
            w0.q.z = s1.u.x; w0.q.w = s1.u.y;
            s0.h[0] = __floats2half2_rn(v2.x, v2.y);
            s0.h[1] = __floats2half2_rn(v2.z, v2.w);
            w1.q.x = s0.u.x; w1.q.y = s0.u.y;
            s1.h[0] = __floats2half2_rn(v3.x, v3.y);
            s1.h[1] = __floats2half2_rn(v3.z, v3.w);
            w1.q.z = s1.u.x; w1.q.w = s1.u.y;
            uint32_t o0 = (uint32_t)(r * 128 + j * 32);
            uint32_t o1 = o0 + 16;
            *(uint4*)(smem + (SMO_A16) + (o0 ^ ((o0 >> 3) & 0x70))) = w0.q;
            *(uint4*)(smem + (SMO_A16) + (o1 ^ ((o1 >> 3) & 0x70))) = w1.q;
        }
        __syncthreads();

        const uint32_t Bbuf = sbB + buf * (NPACK * 128);

#pragma unroll
        for (int ks = 0; ks < 4; ks++) {
            // ---- A fragments via ldmatrix.x4 on fp16 tile ----
            uint32_t af[2][4];
#pragma unroll
            for (int mf = 0; mf < 2; mf++) {
                uint32_t row = (uint32_t)(wm * 32 + mf * 16 + (lid & 15));
                uint32_t off = row * 128 + (uint32_t)(ks * 32 + ((lid >> 4) & 1) * 16);
                uint32_t addr = sbA16 + (off ^ ((off >> 3) & 0x70));
                asm volatile("ldmatrix.sync.aligned.m8n8.x4.shared.b16 {%0,%1,%2,%3}, [%4];"
                             : "=r"(af[mf][0]), "=r"(af[mf][1]),
                               "=r"(af[mf][2]), "=r"(af[mf][3]) : "r"(addr));
            }
            // ---- B fragments + MMA (non-trans: n-major rows, k contiguous) ----
#pragma unroll
            for (int nf = 0; nf < 11; nf++) {
                int row = wn * 88 + nf * 8 + (lid & 7);
                uint32_t off = (uint32_t)(row * 128 + ks * 32 + ((lid >> 3) & 1) * 16);
                uint32_t addr = Bbuf + (off ^ ((off >> 3) & 0x70));
                uint32_t b0, b1;
                asm volatile("ldmatrix.sync.aligned.m8n8.x2.shared.b16 {%0,%1}, [%2];"
                             : "=r"(b0), "=r"(b1) : "r"(addr));
#pragma unroll
                for (int mf = 0; mf < 2; mf++) {
                    asm volatile(
                        "mma.sync.aligned.m16n8k16.row.col.f32.f16.f16.f32 "
                        "{%0,%1,%2,%3},{%4,%5,%6,%7},{%8,%9},{%0,%1,%2,%3};"
                        : "+f"(acc[mf][nf][0]), "+f"(acc[mf][nf][1]),
                          "+f"(acc[mf][nf][2]), "+f"(acc[mf][nf][3])
                        : "r"(af[mf][0]), "r"(af[mf][1]), "r"(af[mf][2]), "r"(af[mf][3]),
                          "r"(b0), "r"(b1));
                }
            }
        }
        __syncthreads();
    }

    // ---- zero the 68 masked class-score columns ----
    {
        int r = tid >> 2, sub = tid & 3;
        float* srow = out + (size_t)(mbase + r) * NSC;
#pragma unroll
        for (int j = sub; j < 80; j += 4)
            if (!cls_keep(j)) srow[1 + j] = 0.0f;
    }

    // ---- scatter accumulators (+bias) ----
#pragma unroll
    for (int mf = 0; mf < 2; mf++) {
#pragma unroll
        for (int half = 0; half < 2; half++) {
            const int m = mbase + wm * 32 + mf * 16 + q + half * 8;
            float* srow = out + (size_t)m * NSC;
            float* brow = out + (size_t)N_TOK * NSC + (size_t)m * NBB;
#pragma unroll
            for (int nf = 0; nf < 11; nf++) {
#pragma unroll
                for (int e = 0; e < 2; e++) {
                    const int c = wn * 88 + nf * 8 + t * 2 + e;
                    float v = acc[mf][nf][half * 2 + e] + s_bias[c];
                    if (c == 0)        srow[0] = v;
                    else if (c <= 12)  srow[1 + c_sel[c - 1]] = v;
                    else if (c <= 336) brow[c - 13] = v;
                }
            }
        }
    }
}

// ---------------------------------------------------------------------------
// Launch
// ---------------------------------------------------------------------------
extern "C" void kernel_launch(void* const* d_in, const int* in_sizes, int n_in,
                              void* d_out, int out_size) {
    const float* x      = (const float*)d_in[0];
    const float* W_cls  = (const float*)d_in[1];
    const float* b_cls  = (const float*)d_in[2];
    const float* W_sem  = (const float*)d_in[3];
    const float* b_sem  = (const float*)d_in[4];
    const float* W_bbox = (const float*)d_in[5];
    const float* b_bbox = (const float*)d_in[6];
    const float* sem_m  = (const float*)d_in[7];
    float* out = (float*)d_out;

    cudaFuncSetAttribute(fpn_gemm, cudaFuncAttributeMaxDynamicSharedMemorySize, SM_TOTAL);

    prep_kernel<<<SEM_BLKS + NPACK, 256>>>(W_cls, b_cls, W_sem, b_sem, W_bbox, b_bbox, sem_m);
    fpn_gemm<<<N_TOK / BM, THREADS, SM_TOTAL>>>(x, out);
}